// round 1
// baseline (speedup 1.0000x reference)
#include <cuda_runtime.h>
#include <math.h>

#define BATCH 4
#define SEQ   2048
#define DM    1024
#define NH    64

// ---------------- scratch (no cudaMalloc allowed) ----------------
__device__ float g_q[BATCH * SEQ * NH];
__device__ float g_k[BATCH * SEQ * NH];
__device__ float g_v[BATCH * SEQ * NH];

// =================================================================
// Kernel 1: fused QKV projection.
// out[row][0:64]=q, [64:128]=k, [128:192]=v,  row = b*SEQ + s
// Block: 64 rows x 192 cols, 256 threads, thread tile 8x6.
// =================================================================
#define PTM 64
#define PKC 16

__global__ __launch_bounds__(256) void qkv_kernel(
    const float* __restrict__ x,
    const float* __restrict__ Wq, const float* __restrict__ bq,
    const float* __restrict__ Wk, const float* __restrict__ bk,
    const float* __restrict__ Wv, const float* __restrict__ bv)
{
    __shared__ float xs[2][PKC][PTM];     // k-major transposed x tile
    __shared__ float ws[2][PKC][192];     // weight tile (q|k|v)

    const int tid  = threadIdx.x;
    const int row0 = blockIdx.x * PTM;

    // x load mapping: one float4 per thread: row = tid/4, k4 = (tid%4)*4
    const int lx_row = tid >> 2;
    const int lx_k   = (tid & 3) << 2;
    // w load mapping: kk = tid/16, h4 = (tid%16)*4 (one float4 per weight)
    const int lw_k = tid >> 4;
    const int lw_h = (tid & 15) << 2;

    // compute mapping: col = c + 32*j (j=0..5), rows r0c + 0..7
    const int c   = tid & 31;
    const int r0c = (tid >> 5) * 8;

    float acc[8][6];
    #pragma unroll
    for (int i = 0; i < 8; i++)
        #pragma unroll
        for (int j = 0; j < 6; j++) acc[i][j] = 0.f;

    // prefetch chunk 0
    float4 px  = *(const float4*)&x[(row0 + lx_row) * DM + lx_k];
    float4 pwq = *(const float4*)&Wq[lw_k * NH + lw_h];
    float4 pwk = *(const float4*)&Wk[lw_k * NH + lw_h];
    float4 pwv = *(const float4*)&Wv[lw_k * NH + lw_h];

    for (int kc = 0; kc < DM; kc += PKC) {
        const int buf = (kc / PKC) & 1;
        xs[buf][lx_k + 0][lx_row] = px.x;
        xs[buf][lx_k + 1][lx_row] = px.y;
        xs[buf][lx_k + 2][lx_row] = px.z;
        xs[buf][lx_k + 3][lx_row] = px.w;
        *(float4*)&ws[buf][lw_k][lw_h]        = pwq;
        *(float4*)&ws[buf][lw_k][64  + lw_h]  = pwk;
        *(float4*)&ws[buf][lw_k][128 + lw_h]  = pwv;
        __syncthreads();

        if (kc + PKC < DM) {
            const int kn = kc + PKC;
            px  = *(const float4*)&x[(row0 + lx_row) * DM + kn + lx_k];
            pwq = *(const float4*)&Wq[(kn + lw_k) * NH + lw_h];
            pwk = *(const float4*)&Wk[(kn + lw_k) * NH + lw_h];
            pwv = *(const float4*)&Wv[(kn + lw_k) * NH + lw_h];
        }

        #pragma unroll
        for (int kk = 0; kk < PKC; kk++) {
            float xv[8];
            float4 xa = *(const float4*)&xs[buf][kk][r0c];
            float4 xb = *(const float4*)&xs[buf][kk][r0c + 4];
            xv[0] = xa.x; xv[1] = xa.y; xv[2] = xa.z; xv[3] = xa.w;
            xv[4] = xb.x; xv[5] = xb.y; xv[6] = xb.z; xv[7] = xb.w;
            float wv[6];
            #pragma unroll
            for (int j = 0; j < 6; j++) wv[j] = ws[buf][kk][c + 32 * j];
            #pragma unroll
            for (int i = 0; i < 8; i++)
                #pragma unroll
                for (int j = 0; j < 6; j++)
                    acc[i][j] += xv[i] * wv[j];
        }
        __syncthreads();
    }

    #pragma unroll
    for (int j = 0; j < 6; j++) {
        const int col = c + 32 * j;
        const int w = col >> 6;
        const int h = col & 63;
        const float bias = (w == 0) ? bq[h] : (w == 1) ? bk[h] : bv[h];
        float* dst = (w == 0) ? g_q : (w == 1) ? g_k : g_v;
        #pragma unroll
        for (int i = 0; i < 8; i++)
            dst[(row0 + r0c + i) * NH + h] = acc[i][j] + bias;
    }
}

// =================================================================
// Kernel 2: causal flash attention.
// Pair scheduling: block (pair,b) handles qtiles {pair, 63-pair}
// (BQ=32) so every block does exactly 33 BK=64 key tiles.
// =================================================================
#define BQ 32
#define BK 64
#define HP 68   // padded row stride (floats): conflict-free LDS.128

__global__ __launch_bounds__(256) void attn_kernel(float* __restrict__ out)
{
    extern __shared__ float sm[];
    float* qs = sm;                        // [BQ][HP]
    float* ks = qs + BQ * HP;              // [2][BK][HP]
    float* vs = ks + 2 * BK * HP;          // [2][BK][HP]
    float* ss = vs + 2 * BK * HP;          // [BQ][HP] (scores / probs)
    float* rm = ss + BQ * HP;              // [BQ]
    float* rl = rm + BQ;                   // [BQ]
    float* rf = rl + BQ;                   // [BQ]

    const int tid  = threadIdx.x;
    const int b    = blockIdx.y;
    const int pair = blockIdx.x;

    const float* Q = g_q + b * SEQ * NH;
    const float* K = g_k + b * SEQ * NH;
    const float* V = g_v + b * SEQ * NH;

    const int qg = tid >> 4;      // 0..15 -> rows {qg, qg+16}
    const int kg = tid & 15;      // S-phase cols {kg+16i}, PV h-cols {4kg..+3}
    const int lt_k  = tid >> 4;   // KV tile load: k-rows {lt_k + 16r}
    const int lt_h4 = (tid & 15) << 2;

    for (int sub = 0; sub < 2; sub++) {
        const int qt = (sub == 0) ? pair : (63 - pair);
        const int q0 = qt * BQ;
        const int nk = (q0 + BQ + BK - 1) / BK;

        __syncthreads();  // previous subtile fully done (rl reads vs re-init)

        // load Q tile (scaled by 1/sqrt(64)), init stats
        #pragma unroll
        for (int it = 0; it < 2; it++) {
            const int i  = tid + it * 256;
            const int r  = i >> 4;
            const int h4 = (i & 15) << 2;
            float4 qv = *(const float4*)&Q[(q0 + r) * NH + h4];
            qv.x *= 0.125f; qv.y *= 0.125f; qv.z *= 0.125f; qv.w *= 0.125f;
            *(float4*)&qs[r * HP + h4] = qv;
        }
        if (tid < BQ) { rm[tid] = -1e30f; rl[tid] = 0.f; }

        float o0[4] = {0.f, 0.f, 0.f, 0.f};
        float o1[4] = {0.f, 0.f, 0.f, 0.f};

        // load key tile 0 directly
        #pragma unroll
        for (int r = 0; r < 4; r++) {
            const int kr = lt_k + 16 * r;
            *(float4*)&ks[0 * BK * HP + kr * HP + lt_h4] =
                *(const float4*)&K[kr * NH + lt_h4];
            *(float4*)&vs[0 * BK * HP + kr * HP + lt_h4] =
                *(const float4*)&V[kr * NH + lt_h4];
        }
        __syncthreads();

        for (int t = 0; t < nk; t++) {
            const int buf = t & 1;
            float* ksb = ks + buf * BK * HP;
            float* vsb = vs + buf * BK * HP;

            // prefetch next KV tile into registers
            float4 pk[4], pv[4];
            if (t + 1 < nk) {
                const int kb = (t + 1) * BK;
                #pragma unroll
                for (int r = 0; r < 4; r++) {
                    const int kr = lt_k + 16 * r;
                    pk[r] = *(const float4*)&K[(kb + kr) * NH + lt_h4];
                    pv[r] = *(const float4*)&V[(kb + kr) * NH + lt_h4];
                }
            }

            // ---- S = Q K^T ----
            float sacc[2][4] = {{0.f,0.f,0.f,0.f},{0.f,0.f,0.f,0.f}};
            #pragma unroll
            for (int h = 0; h < NH; h += 4) {
                float4 qa = *(const float4*)&qs[qg * HP + h];
                float4 qb = *(const float4*)&qs[(qg + 16) * HP + h];
                #pragma unroll
                for (int i = 0; i < 4; i++) {
                    float4 kv = *(const float4*)&ksb[(kg + 16 * i) * HP + h];
                    sacc[0][i] += qa.x*kv.x + qa.y*kv.y + qa.z*kv.z + qa.w*kv.w;
                    sacc[1][i] += qb.x*kv.x + qb.y*kv.y + qb.z*kv.z + qb.w*kv.w;
                }
            }

            // ---- store scores (causal mask on diagonal tile) ----
            const bool maskt = (t == nk - 1);
            #pragma unroll
            for (int i = 0; i < 4; i++) {
                const int cc = kg + 16 * i;
                const int kglob = t * BK + cc;
                float v0 = sacc[0][i], v1 = sacc[1][i];
                if (maskt) {
                    if (kglob > q0 + qg)      v0 = -1e30f;
                    if (kglob > q0 + qg + 16) v1 = -1e30f;
                }
                ss[qg * HP + cc]        = v0;
                ss[(qg + 16) * HP + cc] = v1;
            }
            __syncthreads();

            // ---- online softmax: 8 threads per row, 8 cols each ----
            {
                const int row = tid >> 3;
                const int j   = tid & 7;
                const float m_old = rm[row];
                float lmax = -1e30f;
                #pragma unroll
                for (int cc = 0; cc < 8; cc++)
                    lmax = fmaxf(lmax, ss[row * HP + j * 8 + cc]);
                lmax = fmaxf(lmax, __shfl_xor_sync(0xffffffffu, lmax, 1));
                lmax = fmaxf(lmax, __shfl_xor_sync(0xffffffffu, lmax, 2));
                lmax = fmaxf(lmax, __shfl_xor_sync(0xffffffffu, lmax, 4));
                const float mnew = fmaxf(m_old, lmax);
                float lsum = 0.f;
                #pragma unroll
                for (int cc = 0; cc < 8; cc++) {
                    const float p = __expf(ss[row * HP + j * 8 + cc] - mnew);
                    ss[row * HP + j * 8 + cc] = p;
                    lsum += p;
                }
                lsum += __shfl_xor_sync(0xffffffffu, lsum, 1);
                lsum += __shfl_xor_sync(0xffffffffu, lsum, 2);
                lsum += __shfl_xor_sync(0xffffffffu, lsum, 4);
                if (j == 0) {
                    const float f = __expf(m_old - mnew);
                    rf[row] = f;
                    rl[row] = rl[row] * f + lsum;
                    rm[row] = mnew;
                }
            }
            __syncthreads();

            // ---- O = O*f + P V ----
            {
                const float f0 = rf[qg];
                const float f1 = rf[qg + 16];
                #pragma unroll
                for (int h = 0; h < 4; h++) { o0[h] *= f0; o1[h] *= f1; }
                #pragma unroll 16
                for (int k = 0; k < BK; k++) {
                    const float p0 = ss[qg * HP + k];
                    const float p1 = ss[(qg + 16) * HP + k];
                    float4 vv = *(const float4*)&vsb[k * HP + kg * 4];
                    o0[0] += p0 * vv.x; o0[1] += p0 * vv.y;
                    o0[2] += p0 * vv.z; o0[3] += p0 * vv.w;
                    o1[0] += p1 * vv.x; o1[1] += p1 * vv.y;
                    o1[2] += p1 * vv.z; o1[3] += p1 * vv.w;
                }
            }

            // commit prefetched tile
            if (t + 1 < nk) {
                float* ksn = ks + ((t + 1) & 1) * BK * HP;
                float* vsn = vs + ((t + 1) & 1) * BK * HP;
                #pragma unroll
                for (int r = 0; r < 4; r++) {
                    const int kr = lt_k + 16 * r;
                    *(float4*)&ksn[kr * HP + lt_h4] = pk[r];
                    *(float4*)&vsn[kr * HP + lt_h4] = pv[r];
                }
            }
            __syncthreads();
        }

        // ---- normalize + writeout ----
        {
            const float il0 = 1.f / rl[qg];
            const float il1 = 1.f / rl[qg + 16];
            float4 w0 = make_float4(o0[0]*il0, o0[1]*il0, o0[2]*il0, o0[3]*il0);
            float4 w1 = make_float4(o1[0]*il1, o1[1]*il1, o1[2]*il1, o1[3]*il1);
            *(float4*)&out[(b * SEQ + q0 + qg) * NH + kg * 4]        = w0;
            *(float4*)&out[(b * SEQ + q0 + qg + 16) * NH + kg * 4]   = w1;
        }
    }
}

// =================================================================
// launch
// =================================================================
static const int ATTN_SMEM =
    (BQ * HP + 2 * BK * HP + 2 * BK * HP + BQ * HP + 3 * BQ) * (int)sizeof(float);

extern "C" void kernel_launch(void* const* d_in, const int* in_sizes, int n_in,
                              void* d_out, int out_size)
{
    (void)in_sizes; (void)n_in; (void)out_size;
    const float* x  = (const float*)d_in[0];
    const float* Wq = (const float*)d_in[1];
    const float* bq = (const float*)d_in[2];
    const float* Wk = (const float*)d_in[3];
    const float* bk = (const float*)d_in[4];
    const float* Wv = (const float*)d_in[5];
    const float* bv = (const float*)d_in[6];
    float* out = (float*)d_out;

    // idempotent; ignore return (attribute persists from first call)
    cudaFuncSetAttribute(attn_kernel,
                         cudaFuncAttributeMaxDynamicSharedMemorySize, ATTN_SMEM);

    qkv_kernel<<<(BATCH * SEQ) / PTM, 256>>>(x, Wq, bq, Wk, bk, Wv, bv);
    attn_kernel<<<dim3(32, BATCH), 256, ATTN_SMEM>>>(out);
}

// round 3
// speedup vs baseline: 1.3044x; 1.3044x over previous
#include <cuda_runtime.h>
#include <math.h>
#include <cstdint>

#define BATCH 4
#define SEQ   2048
#define DM    1024
#define NH    64

// ---------------- scratch (no cudaMalloc allowed) ----------------
__device__ float g_q[BATCH * SEQ * NH];
__device__ float g_k[BATCH * SEQ * NH];
__device__ float g_v[BATCH * SEQ * NH];
__device__ float g_wt[192 * DM];   // W^T (q|k|v rows), tf32-rounded bits

__device__ __forceinline__ uint32_t f2tf32(float f) {
    uint32_t r;
    asm("cvt.rna.tf32.f32 %0, %1;" : "=r"(r) : "f"(f));
    return r;
}

// mma.sync m16n8k8 tf32 (sm_80+ PTX; runs on tensor pipe as HMMA)
__device__ __forceinline__ void mma_tf32(float d[4], const uint32_t a[4],
                                         const uint32_t b[2]) {
    asm volatile(
        "mma.sync.aligned.m16n8k8.row.col.f32.tf32.tf32.f32 "
        "{%0,%1,%2,%3}, {%4,%5,%6,%7}, {%8,%9}, {%0,%1,%2,%3};\n"
        : "+f"(d[0]), "+f"(d[1]), "+f"(d[2]), "+f"(d[3])
        : "r"(a[0]), "r"(a[1]), "r"(a[2]), "r"(a[3]),
          "r"(b[0]), "r"(b[1]));
}

// =================================================================
// Kernel 0: transpose W (q|k|v) -> g_wt[192][1024], tf32-rounded.
// =================================================================
__global__ __launch_bounds__(256) void wt_kernel(
    const float* __restrict__ Wq,
    const float* __restrict__ Wk,
    const float* __restrict__ Wv)
{
    __shared__ float t[64][65];
    const int tid = threadIdx.x;
    const int k0  = blockIdx.x * 64;
    const int y   = blockIdx.y;
    const float* W = (y == 0) ? Wq : (y == 1) ? Wk : Wv;

    #pragma unroll
    for (int i = 0; i < 16; i++) {
        const int idx = tid + i * 256;
        const int kk = idx >> 6, nn = idx & 63;
        t[kk][nn] = W[(k0 + kk) * NH + nn];
    }
    __syncthreads();
    #pragma unroll
    for (int i = 0; i < 16; i++) {
        const int idx = tid + i * 256;
        const int nn = idx >> 6, kk = idx & 63;
        g_wt[(y * 64 + nn) * DM + k0 + kk] = __uint_as_float(f2tf32(t[kk][nn]));
    }
}

// =================================================================
// Kernel 1: QKV projection via mma.sync tf32.
// Block: M=64 x N=192, 8 warps (2x4), warp tile 32x48 (2x6 m16n8 tiles).
// K=1024 in 32-chunks, register-prefetch single smem buffer.
// =================================================================
#define APAD 36   // smem row stride (floats) -> conflict-free frag loads

__global__ __launch_bounds__(256) void qkv_mma_kernel(
    const float* __restrict__ x,
    const float* __restrict__ bq,
    const float* __restrict__ bk,
    const float* __restrict__ bv)
{
    __shared__ float As[64][APAD];    // x tile (tf32 bits)
    __shared__ float Bs[192][APAD];   // W^T tile (tf32 bits)
    __shared__ float bias_sm[192];

    const int tid  = threadIdx.x;
    const int wid  = tid >> 5;
    const int lane = tid & 31;
    const int m0   = blockIdx.x * 64;
    const int wm   = wid >> 2;        // 0..1 -> row offset wm*32
    const int wn   = wid & 3;         // 0..3 -> col offset wn*48

    if (tid < 64)        bias_sm[tid] = bq[tid];
    else if (tid < 128)  bias_sm[tid] = bk[tid - 64];
    else if (tid < 192)  bias_sm[tid] = bv[tid - 128];

    const int gid = lane >> 2;        // 0..7
    const int tig = lane & 3;         // 0..3

    float d[2][6][4];
    #pragma unroll
    for (int i = 0; i < 2; i++)
        #pragma unroll
        for (int j = 0; j < 6; j++)
            #pragma unroll
            for (int c = 0; c < 4; c++) d[i][j][c] = 0.f;

    // load mapping: row = idx>>3, c4 = (idx&7)*4
    float4 ra[2], rb[6];
    #pragma unroll
    for (int i = 0; i < 2; i++) {
        const int idx = tid + i * 256;
        ra[i] = *(const float4*)&x[(size_t)(m0 + (idx >> 3)) * DM + ((idx & 7) << 2)];
    }
    #pragma unroll
    for (int i = 0; i < 6; i++) {
        const int idx = tid + i * 256;
        rb[i] = *(const float4*)&g_wt[(size_t)(idx >> 3) * DM + ((idx & 7) << 2)];
    }

    for (int kc = 0; kc < DM; kc += 32) {
        // commit prefetched chunk to smem (A -> tf32 here)
        #pragma unroll
        for (int i = 0; i < 2; i++) {
            const int idx = tid + i * 256;
            uint4 w;
            w.x = f2tf32(ra[i].x); w.y = f2tf32(ra[i].y);
            w.z = f2tf32(ra[i].z); w.w = f2tf32(ra[i].w);
            *(uint4*)&As[idx >> 3][(idx & 7) << 2] = w;
        }
        #pragma unroll
        for (int i = 0; i < 6; i++) {
            const int idx = tid + i * 256;
            *(float4*)&Bs[idx >> 3][(idx & 7) << 2] = rb[i];
        }
        __syncthreads();

        // prefetch next chunk (overlaps compute)
        if (kc + 32 < DM) {
            const int kn = kc + 32;
            #pragma unroll
            for (int i = 0; i < 2; i++) {
                const int idx = tid + i * 256;
                ra[i] = *(const float4*)&x[(size_t)(m0 + (idx >> 3)) * DM + kn + ((idx & 7) << 2)];
            }
            #pragma unroll
            for (int i = 0; i < 6; i++) {
                const int idx = tid + i * 256;
                rb[i] = *(const float4*)&g_wt[(size_t)(idx >> 3) * DM + kn + ((idx & 7) << 2)];
            }
        }

        // 4 k-steps of 8
        #pragma unroll
        for (int ks = 0; ks < 4; ks++) {
            const int k0 = ks * 8;
            uint32_t a[2][4];
            #pragma unroll
            for (int mt = 0; mt < 2; mt++) {
                const int r = wm * 32 + mt * 16 + gid;
                a[mt][0] = *(const uint32_t*)&As[r][k0 + tig];
                a[mt][1] = *(const uint32_t*)&As[r + 8][k0 + tig];
                a[mt][2] = *(const uint32_t*)&As[r][k0 + tig + 4];
                a[mt][3] = *(const uint32_t*)&As[r + 8][k0 + tig + 4];
            }
            #pragma unroll
            for (int nt = 0; nt < 6; nt++) {
                const int n = wn * 48 + nt * 8 + gid;
                uint32_t b[2];
                b[0] = *(const uint32_t*)&Bs[n][k0 + tig];
                b[1] = *(const uint32_t*)&Bs[n][k0 + tig + 4];
                mma_tf32(d[0][nt], a[0], b);
                mma_tf32(d[1][nt], a[1], b);
            }
        }
        __syncthreads();
    }

    // epilogue: bias + store (2 contiguous floats per c-pair)
    #pragma unroll
    for (int mt = 0; mt < 2; mt++) {
        const int row = m0 + wm * 32 + mt * 16 + gid;
        #pragma unroll
        for (int nt = 0; nt < 6; nt++) {
            const int col0 = wn * 48 + nt * 8;
            float* dst = (col0 < 64) ? g_q : (col0 < 128) ? g_k : g_v;
            const int h0 = (col0 & 63) + 2 * tig;
            const float b0 = bias_sm[col0 + 2 * tig];
            const float b1 = bias_sm[col0 + 2 * tig + 1];
            float2 w0 = make_float2(d[mt][nt][0] + b0, d[mt][nt][1] + b1);
            float2 w1 = make_float2(d[mt][nt][2] + b0, d[mt][nt][3] + b1);
            *(float2*)&dst[(size_t)row * NH + h0]       = w0;
            *(float2*)&dst[(size_t)(row + 8) * NH + h0] = w1;
        }
    }
}

// =================================================================
// Kernel 2: causal flash attention (unchanged — known good).
// =================================================================
#define BQ 32
#define BK 64
#define HP 68

__global__ __launch_bounds__(256) void attn_kernel(float* __restrict__ out)
{
    extern __shared__ float sm[];
    float* qs = sm;
    float* ks = qs + BQ * HP;
    float* vs = ks + 2 * BK * HP;
    float* ss = vs + 2 * BK * HP;
    float* rm = ss + BQ * HP;
    float* rl = rm + BQ;
    float* rf = rl + BQ;

    const int tid  = threadIdx.x;
    const int b    = blockIdx.y;
    const int pair = blockIdx.x;

    const float* Q = g_q + b * SEQ * NH;
    const float* K = g_k + b * SEQ * NH;
    const float* V = g_v + b * SEQ * NH;

    const int qg = tid >> 4;
    const int kg = tid & 15;
    const int lt_k  = tid >> 4;
    const int lt_h4 = (tid & 15) << 2;

    for (int sub = 0; sub < 2; sub++) {
        const int qt = (sub == 0) ? pair : (63 - pair);
        const int q0 = qt * BQ;
        const int nk = (q0 + BQ + BK - 1) / BK;

        __syncthreads();

        #pragma unroll
        for (int it = 0; it < 2; it++) {
            const int i  = tid + it * 256;
            const int r  = i >> 4;
            const int h4 = (i & 15) << 2;
            float4 qv = *(const float4*)&Q[(q0 + r) * NH + h4];
            qv.x *= 0.125f; qv.y *= 0.125f; qv.z *= 0.125f; qv.w *= 0.125f;
            *(float4*)&qs[r * HP + h4] = qv;
        }
        if (tid < BQ) { rm[tid] = -1e30f; rl[tid] = 0.f; }

        float o0[4] = {0.f, 0.f, 0.f, 0.f};
        float o1[4] = {0.f, 0.f, 0.f, 0.f};

        #pragma unroll
        for (int r = 0; r < 4; r++) {
            const int kr = lt_k + 16 * r;
            *(float4*)&ks[0 * BK * HP + kr * HP + lt_h4] =
                *(const float4*)&K[kr * NH + lt_h4];
            *(float4*)&vs[0 * BK * HP + kr * HP + lt_h4] =
                *(const float4*)&V[kr * NH + lt_h4];
        }
        __syncthreads();

        for (int t = 0; t < nk; t++) {
            const int buf = t & 1;
            float* ksb = ks + buf * BK * HP;
            float* vsb = vs + buf * BK * HP;

            float4 pk[4], pv[4];
            if (t + 1 < nk) {
                const int kb = (t + 1) * BK;
                #pragma unroll
                for (int r = 0; r < 4; r++) {
                    const int kr = lt_k + 16 * r;
                    pk[r] = *(const float4*)&K[(kb + kr) * NH + lt_h4];
                    pv[r] = *(const float4*)&V[(kb + kr) * NH + lt_h4];
                }
            }

            float sacc[2][4] = {{0.f,0.f,0.f,0.f},{0.f,0.f,0.f,0.f}};
            #pragma unroll
            for (int h = 0; h < NH; h += 4) {
                float4 qa = *(const float4*)&qs[qg * HP + h];
                float4 qb = *(const float4*)&qs[(qg + 16) * HP + h];
                #pragma unroll
                for (int i = 0; i < 4; i++) {
                    float4 kv = *(const float4*)&ksb[(kg + 16 * i) * HP + h];
                    sacc[0][i] += qa.x*kv.x + qa.y*kv.y + qa.z*kv.z + qa.w*kv.w;
                    sacc[1][i] += qb.x*kv.x + qb.y*kv.y + qb.z*kv.z + qb.w*kv.w;
                }
            }

            const bool maskt = (t == nk - 1);
            #pragma unroll
            for (int i = 0; i < 4; i++) {
                const int cc = kg + 16 * i;
                const int kglob = t * BK + cc;
                float v0 = sacc[0][i], v1 = sacc[1][i];
                if (maskt) {
                    if (kglob > q0 + qg)      v0 = -1e30f;
                    if (kglob > q0 + qg + 16) v1 = -1e30f;
                }
                ss[qg * HP + cc]        = v0;
                ss[(qg + 16) * HP + cc] = v1;
            }
            __syncthreads();

            {
                const int row = tid >> 3;
                const int j   = tid & 7;
                const float m_old = rm[row];
                float lmax = -1e30f;
                #pragma unroll
                for (int cc = 0; cc < 8; cc++)
                    lmax = fmaxf(lmax, ss[row * HP + j * 8 + cc]);
                lmax = fmaxf(lmax, __shfl_xor_sync(0xffffffffu, lmax, 1));
                lmax = fmaxf(lmax, __shfl_xor_sync(0xffffffffu, lmax, 2));
                lmax = fmaxf(lmax, __shfl_xor_sync(0xffffffffu, lmax, 4));
                const float mnew = fmaxf(m_old, lmax);
                float lsum = 0.f;
                #pragma unroll
                for (int cc = 0; cc < 8; cc++) {
                    const float p = __expf(ss[row * HP + j * 8 + cc] - mnew);
                    ss[row * HP + j * 8 + cc] = p;
                    lsum += p;
                }
                lsum += __shfl_xor_sync(0xffffffffu, lsum, 1);
                lsum += __shfl_xor_sync(0xffffffffu, lsum, 2);
                lsum += __shfl_xor_sync(0xffffffffu, lsum, 4);
                if (j == 0) {
                    const float f = __expf(m_old - mnew);
                    rf[row] = f;
                    rl[row] = rl[row] * f + lsum;
                    rm[row] = mnew;
                }
            }
            __syncthreads();

            {
                const float f0 = rf[qg];
                const float f1 = rf[qg + 16];
                #pragma unroll
                for (int h = 0; h < 4; h++) { o0[h] *= f0; o1[h] *= f1; }
                #pragma unroll 16
                for (int k = 0; k < BK; k++) {
                    const float p0 = ss[qg * HP + k];
                    const float p1 = ss[(qg + 16) * HP + k];
                    float4 vv = *(const float4*)&vsb[k * HP + kg * 4];
                    o0[0] += p0 * vv.x; o0[1] += p0 * vv.y;
                    o0[2] += p0 * vv.z; o0[3] += p0 * vv.w;
                    o1[0] += p1 * vv.x; o1[1] += p1 * vv.y;
                    o1[2] += p1 * vv.z; o1[3] += p1 * vv.w;
                }
            }

            if (t + 1 < nk) {
                float* ksn = ks + ((t + 1) & 1) * BK * HP;
                float* vsn = vs + ((t + 1) & 1) * BK * HP;
                #pragma unroll
                for (int r = 0; r < 4; r++) {
                    const int kr = lt_k + 16 * r;
                    *(float4*)&ksn[kr * HP + lt_h4] = pk[r];
                    *(float4*)&vsn[kr * HP + lt_h4] = pv[r];
                }
            }
            __syncthreads();
        }

        {
            const float il0 = 1.f / rl[qg];
            const float il1 = 1.f / rl[qg + 16];
            float4 w0 = make_float4(o0[0]*il0, o0[1]*il0, o0[2]*il0, o0[3]*il0);
            float4 w1 = make_float4(o1[0]*il1, o1[1]*il1, o1[2]*il1, o1[3]*il1);
            *(float4*)&out[(b * SEQ + q0 + qg) * NH + kg * 4]        = w0;
            *(float4*)&out[(b * SEQ + q0 + qg + 16) * NH + kg * 4]   = w1;
        }
    }
}

// =================================================================
// launch
// =================================================================
static const int ATTN_SMEM =
    (BQ * HP + 2 * BK * HP + 2 * BK * HP + BQ * HP + 3 * BQ) * (int)sizeof(float);

extern "C" void kernel_launch(void* const* d_in, const int* in_sizes, int n_in,
                              void* d_out, int out_size)
{
    (void)in_sizes; (void)n_in; (void)out_size;
    const float* x  = (const float*)d_in[0];
    const float* Wq = (const float*)d_in[1];
    const float* bq = (const float*)d_in[2];
    const float* Wk = (const float*)d_in[3];
    const float* bk = (const float*)d_in[4];
    const float* Wv = (const float*)d_in[5];
    const float* bv = (const float*)d_in[6];
    float* out = (float*)d_out;

    cudaFuncSetAttribute(attn_kernel,
                         cudaFuncAttributeMaxDynamicSharedMemorySize, ATTN_SMEM);

    wt_kernel<<<dim3(16, 3), 256>>>(Wq, Wk, Wv);
    qkv_mma_kernel<<<(BATCH * SEQ) / 64, 256>>>(x, bq, bk, bv);
    attn_kernel<<<dim3(32, BATCH), 256, ATTN_SMEM>>>(out);
}

// round 4
// speedup vs baseline: 2.0356x; 1.5606x over previous
#include <cuda_runtime.h>
#include <math.h>
#include <cstdint>

#define BATCH 4
#define SEQ   2048
#define DM    1024
#define NH    64

// ---------------- scratch (no cudaMalloc allowed) ----------------
__device__ float g_q[BATCH * SEQ * NH];
__device__ float g_k[BATCH * SEQ * NH];
__device__ float g_v[BATCH * SEQ * NH];
__device__ float g_wt[192 * DM];   // W^T (q|k|v rows), tf32-rounded bits

__device__ __forceinline__ uint32_t f2tf32(float f) {
    uint32_t r;
    asm("cvt.rna.tf32.f32 %0, %1;" : "=r"(r) : "f"(f));
    return r;
}

__device__ __forceinline__ uint4 conv4(float4 v) {
    uint4 u;
    u.x = f2tf32(v.x); u.y = f2tf32(v.y);
    u.z = f2tf32(v.z); u.w = f2tf32(v.w);
    return u;
}

// mma.sync m16n8k8 tf32 (sm_80+ PTX; runs on tensor pipe)
__device__ __forceinline__ void mma_tf32(float d[4], const uint32_t a[4],
                                         const uint32_t b[2]) {
    asm volatile(
        "mma.sync.aligned.m16n8k8.row.col.f32.tf32.tf32.f32 "
        "{%0,%1,%2,%3}, {%4,%5,%6,%7}, {%8,%9}, {%0,%1,%2,%3};\n"
        : "+f"(d[0]), "+f"(d[1]), "+f"(d[2]), "+f"(d[3])
        : "r"(a[0]), "r"(a[1]), "r"(a[2]), "r"(a[3]),
          "r"(b[0]), "r"(b[1]));
}

// =================================================================
// Kernel 0: transpose W (q|k|v) -> g_wt[192][1024], tf32-rounded.
// =================================================================
__global__ __launch_bounds__(256) void wt_kernel(
    const float* __restrict__ Wq,
    const float* __restrict__ Wk,
    const float* __restrict__ Wv)
{
    __shared__ float t[64][65];
    const int tid = threadIdx.x;
    const int k0  = blockIdx.x * 64;
    const int y   = blockIdx.y;
    const float* W = (y == 0) ? Wq : (y == 1) ? Wk : Wv;

    #pragma unroll
    for (int i = 0; i < 16; i++) {
        const int idx = tid + i * 256;
        const int kk = idx >> 6, nn = idx & 63;
        t[kk][nn] = W[(k0 + kk) * NH + nn];
    }
    __syncthreads();
    #pragma unroll
    for (int i = 0; i < 16; i++) {
        const int idx = tid + i * 256;
        const int nn = idx >> 6, kk = idx & 63;
        g_wt[(y * 64 + nn) * DM + k0 + kk] = __uint_as_float(f2tf32(t[kk][nn]));
    }
}

// =================================================================
// Kernel 1: QKV projection via mma.sync tf32 (unchanged — passing).
// =================================================================
#define APAD 36

__global__ __launch_bounds__(256) void qkv_mma_kernel(
    const float* __restrict__ x,
    const float* __restrict__ bq,
    const float* __restrict__ bk,
    const float* __restrict__ bv)
{
    __shared__ float As[64][APAD];
    __shared__ float Bs[192][APAD];
    __shared__ float bias_sm[192];

    const int tid  = threadIdx.x;
    const int wid  = tid >> 5;
    const int lane = tid & 31;
    const int m0   = blockIdx.x * 64;
    const int wm   = wid >> 2;
    const int wn   = wid & 3;

    if (tid < 64)        bias_sm[tid] = bq[tid];
    else if (tid < 128)  bias_sm[tid] = bk[tid - 64];
    else if (tid < 192)  bias_sm[tid] = bv[tid - 128];

    const int gid = lane >> 2;
    const int tig = lane & 3;

    float d[2][6][4];
    #pragma unroll
    for (int i = 0; i < 2; i++)
        #pragma unroll
        for (int j = 0; j < 6; j++)
            #pragma unroll
            for (int c = 0; c < 4; c++) d[i][j][c] = 0.f;

    float4 ra[2], rb[6];
    #pragma unroll
    for (int i = 0; i < 2; i++) {
        const int idx = tid + i * 256;
        ra[i] = *(const float4*)&x[(size_t)(m0 + (idx >> 3)) * DM + ((idx & 7) << 2)];
    }
    #pragma unroll
    for (int i = 0; i < 6; i++) {
        const int idx = tid + i * 256;
        rb[i] = *(const float4*)&g_wt[(size_t)(idx >> 3) * DM + ((idx & 7) << 2)];
    }

    for (int kc = 0; kc < DM; kc += 32) {
        #pragma unroll
        for (int i = 0; i < 2; i++) {
            const int idx = tid + i * 256;
            *(uint4*)&As[idx >> 3][(idx & 7) << 2] = conv4(ra[i]);
        }
        #pragma unroll
        for (int i = 0; i < 6; i++) {
            const int idx = tid + i * 256;
            *(float4*)&Bs[idx >> 3][(idx & 7) << 2] = rb[i];
        }
        __syncthreads();

        if (kc + 32 < DM) {
            const int kn = kc + 32;
            #pragma unroll
            for (int i = 0; i < 2; i++) {
                const int idx = tid + i * 256;
                ra[i] = *(const float4*)&x[(size_t)(m0 + (idx >> 3)) * DM + kn + ((idx & 7) << 2)];
            }
            #pragma unroll
            for (int i = 0; i < 6; i++) {
                const int idx = tid + i * 256;
                rb[i] = *(const float4*)&g_wt[(size_t)(idx >> 3) * DM + kn + ((idx & 7) << 2)];
            }
        }

        #pragma unroll
        for (int ks = 0; ks < 4; ks++) {
            const int k0 = ks * 8;
            uint32_t a[2][4];
            #pragma unroll
            for (int mt = 0; mt < 2; mt++) {
                const int r = wm * 32 + mt * 16 + gid;
                a[mt][0] = *(const uint32_t*)&As[r][k0 + tig];
                a[mt][1] = *(const uint32_t*)&As[r + 8][k0 + tig];
                a[mt][2] = *(const uint32_t*)&As[r][k0 + tig + 4];
                a[mt][3] = *(const uint32_t*)&As[r + 8][k0 + tig + 4];
            }
            #pragma unroll
            for (int nt = 0; nt < 6; nt++) {
                const int n = wn * 48 + nt * 8 + gid;
                uint32_t b[2];
                b[0] = *(const uint32_t*)&Bs[n][k0 + tig];
                b[1] = *(const uint32_t*)&Bs[n][k0 + tig + 4];
                mma_tf32(d[0][nt], a[0], b);
                mma_tf32(d[1][nt], a[1], b);
            }
        }
        __syncthreads();
    }

    #pragma unroll
    for (int mt = 0; mt < 2; mt++) {
        const int row = m0 + wm * 32 + mt * 16 + gid;
        #pragma unroll
        for (int nt = 0; nt < 6; nt++) {
            const int col0 = wn * 48 + nt * 8;
            float* dst = (col0 < 64) ? g_q : (col0 < 128) ? g_k : g_v;
            const int h0 = (col0 & 63) + 2 * tig;
            const float b0 = bias_sm[col0 + 2 * tig];
            const float b1 = bias_sm[col0 + 2 * tig + 1];
            float2 w0 = make_float2(d[mt][nt][0] + b0, d[mt][nt][1] + b1);
            float2 w1 = make_float2(d[mt][nt][2] + b0, d[mt][nt][3] + b1);
            *(float2*)&dst[(size_t)row * NH + h0]       = w0;
            *(float2*)&dst[(size_t)(row + 8) * NH + h0] = w1;
        }
    }
}

// =================================================================
// Kernel 2: causal flash attention with mma.sync tf32 for S and PV.
// BQ=32, BK=64, 8 warps; warp tile m16 x n16 (wm = wid>>2, wn = wid&3).
// Pair scheduling: block handles qtiles {pair, 63-pair} -> 33 tiles each.
// =================================================================
#define BQ 32
#define BK 64
#define HP 68

__global__ __launch_bounds__(256) void attn_kernel(float* __restrict__ out)
{
    extern __shared__ float sm[];
    float* qs = sm;                  // [BQ][HP] tf32 bits, pre-scaled
    float* ks = qs + BQ * HP;        // [2][BK][HP] tf32 bits
    float* vs = ks + 2 * BK * HP;    // [2][BK][HP] tf32 bits
    float* ss = vs + 2 * BK * HP;    // [BQ][HP] scores / probs(tf32)
    float* rm = ss + BQ * HP;        // [BQ]
    float* rl = rm + BQ;             // [BQ]
    float* rf = rl + BQ;             // [BQ]

    const int tid  = threadIdx.x;
    const int b    = blockIdx.y;
    const int pair = blockIdx.x;

    const float* Q = g_q + b * SEQ * NH;
    const float* K = g_k + b * SEQ * NH;
    const float* V = g_v + b * SEQ * NH;

    const int wid  = tid >> 5;
    const int lane = tid & 31;
    const int gid  = lane >> 2;      // 0..7
    const int tig  = lane & 3;       // 0..3
    const int wm   = wid >> 2;       // 0..1 : row block wm*16
    const int wn   = wid & 3;        // 0..3 : col block wn*16

    for (int sub = 0; sub < 2; sub++) {
        const int qt = (sub == 0) ? pair : (63 - pair);
        const int q0 = qt * BQ;
        const int nk = (q0 + BQ + BK - 1) / BK;

        __syncthreads();  // previous subtile fully done

        // load Q tile: scale by 1/8, convert to tf32
        #pragma unroll
        for (int it = 0; it < 2; it++) {
            const int i  = tid + it * 256;
            const int r  = i >> 4;
            const int h4 = (i & 15) << 2;
            float4 qv = *(const float4*)&Q[(q0 + r) * NH + h4];
            qv.x *= 0.125f; qv.y *= 0.125f; qv.z *= 0.125f; qv.w *= 0.125f;
            *(uint4*)&qs[r * HP + h4] = conv4(qv);
        }
        if (tid < BQ) { rm[tid] = -1e30f; rl[tid] = 0.f; }

        float d_o[2][4];
        #pragma unroll
        for (int nt = 0; nt < 2; nt++)
            #pragma unroll
            for (int c = 0; c < 4; c++) d_o[nt][c] = 0.f;

        // load KV tile 0 directly (tf32)
        #pragma unroll
        for (int i = 0; i < 4; i++) {
            const int idx = tid + i * 256;
            const int kr  = idx >> 4;
            const int h4  = (idx & 15) << 2;
            *(uint4*)&ks[kr * HP + h4] = conv4(*(const float4*)&K[kr * NH + h4]);
            *(uint4*)&vs[kr * HP + h4] = conv4(*(const float4*)&V[kr * NH + h4]);
        }
        __syncthreads();

        for (int t = 0; t < nk; t++) {
            const int buf = t & 1;
            float* ksb = ks + buf * BK * HP;
            float* vsb = vs + buf * BK * HP;

            // prefetch next KV tile into registers
            float4 pk[4], pv[4];
            if (t + 1 < nk) {
                const int kb = (t + 1) * BK;
                #pragma unroll
                for (int i = 0; i < 4; i++) {
                    const int idx = tid + i * 256;
                    const int kr  = idx >> 4;
                    const int h4  = (idx & 15) << 2;
                    pk[i] = *(const float4*)&K[(kb + kr) * NH + h4];
                    pv[i] = *(const float4*)&V[(kb + kr) * NH + h4];
                }
            }

            // ---- S = Q K^T via mma ----
            float sd[2][4];
            #pragma unroll
            for (int nt = 0; nt < 2; nt++)
                #pragma unroll
                for (int c = 0; c < 4; c++) sd[nt][c] = 0.f;

            #pragma unroll
            for (int ks8 = 0; ks8 < 8; ks8++) {
                const int k0 = ks8 * 8;
                uint32_t a[4];
                const int r = wm * 16 + gid;
                a[0] = *(const uint32_t*)&qs[r * HP + k0 + tig];
                a[1] = *(const uint32_t*)&qs[(r + 8) * HP + k0 + tig];
                a[2] = *(const uint32_t*)&qs[r * HP + k0 + tig + 4];
                a[3] = *(const uint32_t*)&qs[(r + 8) * HP + k0 + tig + 4];
                #pragma unroll
                for (int nt = 0; nt < 2; nt++) {
                    const int n = wn * 16 + nt * 8 + gid;
                    uint32_t bb[2];
                    bb[0] = *(const uint32_t*)&ksb[n * HP + k0 + tig];
                    bb[1] = *(const uint32_t*)&ksb[n * HP + k0 + tig + 4];
                    mma_tf32(sd[nt], a, bb);
                }
            }

            // ---- store S to smem with causal mask ----
            {
                const bool maskt = (t == nk - 1);
                const int r0 = wm * 16 + gid;
                const int r1 = r0 + 8;
                #pragma unroll
                for (int nt = 0; nt < 2; nt++) {
                    const int cc = wn * 16 + nt * 8 + 2 * tig;
                    const int kg = t * BK + cc;
                    float v00 = sd[nt][0], v01 = sd[nt][1];
                    float v10 = sd[nt][2], v11 = sd[nt][3];
                    if (maskt) {
                        if (kg     > q0 + r0) v00 = -1e30f;
                        if (kg + 1 > q0 + r0) v01 = -1e30f;
                        if (kg     > q0 + r1) v10 = -1e30f;
                        if (kg + 1 > q0 + r1) v11 = -1e30f;
                    }
                    *(float2*)&ss[r0 * HP + cc] = make_float2(v00, v01);
                    *(float2*)&ss[r1 * HP + cc] = make_float2(v10, v11);
                }
            }
            __syncthreads();

            // ---- online softmax: 8 threads per row, 8 cols each ----
            {
                const int row = tid >> 3;
                const int j   = tid & 7;
                const float m_old = rm[row];
                float lmax = -1e30f;
                #pragma unroll
                for (int cc = 0; cc < 8; cc++)
                    lmax = fmaxf(lmax, ss[row * HP + j * 8 + cc]);
                lmax = fmaxf(lmax, __shfl_xor_sync(0xffffffffu, lmax, 1));
                lmax = fmaxf(lmax, __shfl_xor_sync(0xffffffffu, lmax, 2));
                lmax = fmaxf(lmax, __shfl_xor_sync(0xffffffffu, lmax, 4));
                const float mnew = fmaxf(m_old, lmax);
                float lsum = 0.f;
                #pragma unroll
                for (int cc = 0; cc < 8; cc++) {
                    const float p  = __expf(ss[row * HP + j * 8 + cc] - mnew);
                    const float pr = __uint_as_float(f2tf32(p));
                    ss[row * HP + j * 8 + cc] = pr;
                    lsum += pr;
                }
                lsum += __shfl_xor_sync(0xffffffffu, lsum, 1);
                lsum += __shfl_xor_sync(0xffffffffu, lsum, 2);
                lsum += __shfl_xor_sync(0xffffffffu, lsum, 4);
                if (j == 0) {
                    const float f = __expf(m_old - mnew);
                    rf[row] = f;
                    rl[row] = rl[row] * f + lsum;
                    rm[row] = mnew;
                }
            }
            __syncthreads();

            // ---- O = O*f + P V via mma ----
            {
                const float f0 = rf[wm * 16 + gid];
                const float f1 = rf[wm * 16 + gid + 8];
                #pragma unroll
                for (int nt = 0; nt < 2; nt++) {
                    d_o[nt][0] *= f0; d_o[nt][1] *= f0;
                    d_o[nt][2] *= f1; d_o[nt][3] *= f1;
                }
                #pragma unroll
                for (int ks8 = 0; ks8 < 8; ks8++) {
                    const int k0 = ks8 * 8;
                    uint32_t a[4];
                    const int r = wm * 16 + gid;
                    a[0] = *(const uint32_t*)&ss[r * HP + k0 + tig];
                    a[1] = *(const uint32_t*)&ss[(r + 8) * HP + k0 + tig];
                    a[2] = *(const uint32_t*)&ss[r * HP + k0 + tig + 4];
                    a[3] = *(const uint32_t*)&ss[(r + 8) * HP + k0 + tig + 4];
                    #pragma unroll
                    for (int nt = 0; nt < 2; nt++) {
                        const int n = wn * 16 + nt * 8 + gid;
                        uint32_t bb[2];
                        bb[0] = *(const uint32_t*)&vsb[(k0 + tig) * HP + n];
                        bb[1] = *(const uint32_t*)&vsb[(k0 + tig + 4) * HP + n];
                        mma_tf32(d_o[nt], a, bb);
                    }
                }
            }

            // commit prefetched KV tile (tf32) into other buffer
            if (t + 1 < nk) {
                float* ksn = ks + ((t + 1) & 1) * BK * HP;
                float* vsn = vs + ((t + 1) & 1) * BK * HP;
                #pragma unroll
                for (int i = 0; i < 4; i++) {
                    const int idx = tid + i * 256;
                    const int kr  = idx >> 4;
                    const int h4  = (idx & 15) << 2;
                    *(uint4*)&ksn[kr * HP + h4] = conv4(pk[i]);
                    *(uint4*)&vsn[kr * HP + h4] = conv4(pv[i]);
                }
            }
            __syncthreads();
        }

        // ---- normalize + writeout ----
        {
            const int r0 = wm * 16 + gid;
            const int r1 = r0 + 8;
            const float il0 = 1.f / rl[r0];
            const float il1 = 1.f / rl[r1];
            #pragma unroll
            for (int nt = 0; nt < 2; nt++) {
                const int cc = wn * 16 + nt * 8 + 2 * tig;
                *(float2*)&out[(b * SEQ + q0 + r0) * NH + cc] =
                    make_float2(d_o[nt][0] * il0, d_o[nt][1] * il0);
                *(float2*)&out[(b * SEQ + q0 + r1) * NH + cc] =
                    make_float2(d_o[nt][2] * il1, d_o[nt][3] * il1);
            }
        }
    }
}

// =================================================================
// launch
// =================================================================
static const int ATTN_SMEM =
    (BQ * HP + 2 * BK * HP + 2 * BK * HP + BQ * HP + 3 * BQ) * (int)sizeof(float);

extern "C" void kernel_launch(void* const* d_in, const int* in_sizes, int n_in,
                              void* d_out, int out_size)
{
    (void)in_sizes; (void)n_in; (void)out_size;
    const float* x  = (const float*)d_in[0];
    const float* Wq = (const float*)d_in[1];
    const float* bq = (const float*)d_in[2];
    const float* Wk = (const float*)d_in[3];
    const float* bk = (const float*)d_in[4];
    const float* Wv = (const float*)d_in[5];
    const float* bv = (const float*)d_in[6];
    float* out = (float*)d_out;

    cudaFuncSetAttribute(attn_kernel,
                         cudaFuncAttributeMaxDynamicSharedMemorySize, ATTN_SMEM);

    wt_kernel<<<dim3(16, 3), 256>>>(Wq, Wk, Wv);
    qkv_mma_kernel<<<(BATCH * SEQ) / 64, 256>>>(x, bq, bk, bv);
    attn_kernel<<<dim3(32, BATCH), 256, ATTN_SMEM>>>(out);
}

// round 5
// speedup vs baseline: 2.4655x; 1.2112x over previous
#include <cuda_runtime.h>
#include <math.h>
#include <cstdint>

#define BATCH 4
#define SEQ   2048
#define DM    1024
#define NH    64

// ---------------- scratch (no cudaMalloc allowed) ----------------
__device__ float g_q[BATCH * SEQ * NH];
__device__ float g_k[BATCH * SEQ * NH];
__device__ float g_v[BATCH * SEQ * NH];
__device__ float g_wt[192 * DM];   // W^T (q|k|v rows), tf32-rounded bits

__device__ __forceinline__ uint32_t f2tf32(float f) {
    uint32_t r;
    asm("cvt.rna.tf32.f32 %0, %1;" : "=r"(r) : "f"(f));
    return r;
}

__device__ __forceinline__ uint4 conv4(float4 v) {
    uint4 u;
    u.x = f2tf32(v.x); u.y = f2tf32(v.y);
    u.z = f2tf32(v.z); u.w = f2tf32(v.w);
    return u;
}

// mma.sync m16n8k8 tf32 (sm_80+ PTX; runs on tensor pipe)
__device__ __forceinline__ void mma_tf32(float d[4], const uint32_t a[4],
                                         const uint32_t b[2]) {
    asm volatile(
        "mma.sync.aligned.m16n8k8.row.col.f32.tf32.tf32.f32 "
        "{%0,%1,%2,%3}, {%4,%5,%6,%7}, {%8,%9}, {%0,%1,%2,%3};\n"
        : "+f"(d[0]), "+f"(d[1]), "+f"(d[2]), "+f"(d[3])
        : "r"(a[0]), "r"(a[1]), "r"(a[2]), "r"(a[3]),
          "r"(b[0]), "r"(b[1]));
}

// =================================================================
// Kernel 0: transpose W (q|k|v) -> g_wt[192][1024], tf32-rounded.
// =================================================================
__global__ __launch_bounds__(256) void wt_kernel(
    const float* __restrict__ Wq,
    const float* __restrict__ Wk,
    const float* __restrict__ Wv)
{
    __shared__ float t[64][65];
    const int tid = threadIdx.x;
    const int k0  = blockIdx.x * 64;
    const int y   = blockIdx.y;
    const float* W = (y == 0) ? Wq : (y == 1) ? Wk : Wv;

    #pragma unroll
    for (int i = 0; i < 16; i++) {
        const int idx = tid + i * 256;
        const int kk = idx >> 6, nn = idx & 63;
        t[kk][nn] = W[(k0 + kk) * NH + nn];
    }
    __syncthreads();
    #pragma unroll
    for (int i = 0; i < 16; i++) {
        const int idx = tid + i * 256;
        const int nn = idx >> 6, kk = idx & 63;
        g_wt[(y * 64 + nn) * DM + k0 + kk] = __uint_as_float(f2tf32(t[kk][nn]));
    }
}

// =================================================================
// Kernel 1: QKV projection via mma.sync tf32 (unchanged — passing).
// =================================================================
#define APAD 36

__global__ __launch_bounds__(256) void qkv_mma_kernel(
    const float* __restrict__ x,
    const float* __restrict__ bq,
    const float* __restrict__ bk,
    const float* __restrict__ bv)
{
    __shared__ float As[64][APAD];
    __shared__ float Bs[192][APAD];
    __shared__ float bias_sm[192];

    const int tid  = threadIdx.x;
    const int wid  = tid >> 5;
    const int lane = tid & 31;
    const int m0   = blockIdx.x * 64;
    const int wm   = wid >> 2;
    const int wn   = wid & 3;

    if (tid < 64)        bias_sm[tid] = bq[tid];
    else if (tid < 128)  bias_sm[tid] = bk[tid - 64];
    else if (tid < 192)  bias_sm[tid] = bv[tid - 128];

    const int gid = lane >> 2;
    const int tig = lane & 3;

    float d[2][6][4];
    #pragma unroll
    for (int i = 0; i < 2; i++)
        #pragma unroll
        for (int j = 0; j < 6; j++)
            #pragma unroll
            for (int c = 0; c < 4; c++) d[i][j][c] = 0.f;

    float4 ra[2], rb[6];
    #pragma unroll
    for (int i = 0; i < 2; i++) {
        const int idx = tid + i * 256;
        ra[i] = *(const float4*)&x[(size_t)(m0 + (idx >> 3)) * DM + ((idx & 7) << 2)];
    }
    #pragma unroll
    for (int i = 0; i < 6; i++) {
        const int idx = tid + i * 256;
        rb[i] = *(const float4*)&g_wt[(size_t)(idx >> 3) * DM + ((idx & 7) << 2)];
    }

    for (int kc = 0; kc < DM; kc += 32) {
        #pragma unroll
        for (int i = 0; i < 2; i++) {
            const int idx = tid + i * 256;
            *(uint4*)&As[idx >> 3][(idx & 7) << 2] = conv4(ra[i]);
        }
        #pragma unroll
        for (int i = 0; i < 6; i++) {
            const int idx = tid + i * 256;
            *(float4*)&Bs[idx >> 3][(idx & 7) << 2] = rb[i];
        }
        __syncthreads();

        if (kc + 32 < DM) {
            const int kn = kc + 32;
            #pragma unroll
            for (int i = 0; i < 2; i++) {
                const int idx = tid + i * 256;
                ra[i] = *(const float4*)&x[(size_t)(m0 + (idx >> 3)) * DM + kn + ((idx & 7) << 2)];
            }
            #pragma unroll
            for (int i = 0; i < 6; i++) {
                const int idx = tid + i * 256;
                rb[i] = *(const float4*)&g_wt[(size_t)(idx >> 3) * DM + kn + ((idx & 7) << 2)];
            }
        }

        #pragma unroll
        for (int ks = 0; ks < 4; ks++) {
            const int k0 = ks * 8;
            uint32_t a[2][4];
            #pragma unroll
            for (int mt = 0; mt < 2; mt++) {
                const int r = wm * 32 + mt * 16 + gid;
                a[mt][0] = *(const uint32_t*)&As[r][k0 + tig];
                a[mt][1] = *(const uint32_t*)&As[r + 8][k0 + tig];
                a[mt][2] = *(const uint32_t*)&As[r][k0 + tig + 4];
                a[mt][3] = *(const uint32_t*)&As[r + 8][k0 + tig + 4];
            }
            #pragma unroll
            for (int nt = 0; nt < 6; nt++) {
                const int n = wn * 48 + nt * 8 + gid;
                uint32_t b[2];
                b[0] = *(const uint32_t*)&Bs[n][k0 + tig];
                b[1] = *(const uint32_t*)&Bs[n][k0 + tig + 4];
                mma_tf32(d[0][nt], a[0], b);
                mma_tf32(d[1][nt], a[1], b);
            }
        }
        __syncthreads();
    }

    #pragma unroll
    for (int mt = 0; mt < 2; mt++) {
        const int row = m0 + wm * 32 + mt * 16 + gid;
        #pragma unroll
        for (int nt = 0; nt < 6; nt++) {
            const int col0 = wn * 48 + nt * 8;
            float* dst = (col0 < 64) ? g_q : (col0 < 128) ? g_k : g_v;
            const int h0 = (col0 & 63) + 2 * tig;
            const float b0 = bias_sm[col0 + 2 * tig];
            const float b1 = bias_sm[col0 + 2 * tig + 1];
            float2 w0 = make_float2(d[mt][nt][0] + b0, d[mt][nt][1] + b1);
            float2 w1 = make_float2(d[mt][nt][2] + b0, d[mt][nt][3] + b1);
            *(float2*)&dst[(size_t)row * NH + h0]       = w0;
            *(float2*)&dst[(size_t)(row + 8) * NH + h0] = w1;
        }
    }
}

// =================================================================
// Kernel 2: causal flash attention, mma.sync tf32, register softmax.
// BQ=32, BK=64, 8 warps (wm = wid>>2 rows, wn = wid&3 cols).
// Per tile: 2 barriers; S stays in regs; P written once (exp'd, tf32).
// K smem stride 68 (S-phase conflict-free), V stride 72 (PV conflict-free).
// =================================================================
#define BQ  32
#define BK  64
#define HPK 68
#define HPV 72

__global__ __launch_bounds__(256) void attn_kernel(float* __restrict__ out)
{
    extern __shared__ float sm[];
    float* qs   = sm;                     // [32][68] tf32 (pre-scaled)
    float* ks   = qs + BQ * HPK;          // [2][64][68] tf32
    float* vs   = ks + 2 * BK * HPK;      // [2][64][72] tf32
    float* ss   = vs + 2 * BK * HPV;      // [32][68] P (exp'd, tf32)
    float* pmax = ss + BQ * HPK;          // [32][4]
    float* psum = pmax + 128;             // [32][4]
    float* rm   = psum + 128;             // [32]
    float* rl   = rm + 32;                // [32]

    const int tid  = threadIdx.x;
    const int b    = blockIdx.y;
    const int pair = blockIdx.x;

    const float* Q = g_q + b * SEQ * NH;
    const float* K = g_k + b * SEQ * NH;
    const float* V = g_v + b * SEQ * NH;

    const int wid  = tid >> 5;
    const int lane = tid & 31;
    const int gid  = lane >> 2;
    const int tig  = lane & 3;
    const int wm   = wid >> 2;
    const int wn   = wid & 3;
    const int r0   = wm * 16 + gid;
    const int r1   = r0 + 8;

    for (int sub = 0; sub < 2; sub++) {
        const int qt = (sub == 0) ? pair : (63 - pair);
        const int q0 = qt * BQ;
        const int nk = (q0 + BQ + BK - 1) / BK;

        __syncthreads();  // previous subtile fully done

        // load Q tile: scale by 1/8, convert to tf32
        #pragma unroll
        for (int it = 0; it < 2; it++) {
            const int i  = tid + it * 256;
            const int r  = i >> 4;
            const int h4 = (i & 15) << 2;
            float4 qv = *(const float4*)&Q[(q0 + r) * NH + h4];
            qv.x *= 0.125f; qv.y *= 0.125f; qv.z *= 0.125f; qv.w *= 0.125f;
            *(uint4*)&qs[r * HPK + h4] = conv4(qv);
        }
        if (tid < BQ) { rm[tid] = -1e30f; rl[tid] = 0.f; }

        // load KV tile 0 (tf32)
        #pragma unroll
        for (int i = 0; i < 4; i++) {
            const int idx = tid + i * 256;
            const int kr  = idx >> 4;
            const int h4  = (idx & 15) << 2;
            *(uint4*)&ks[kr * HPK + h4] = conv4(*(const float4*)&K[kr * NH + h4]);
            *(uint4*)&vs[kr * HPV + h4] = conv4(*(const float4*)&V[kr * NH + h4]);
        }
        __syncthreads();

        // hoist Q A-fragments (invariant over the tile loop)
        uint32_t qa[8][4];
        #pragma unroll
        for (int ks8 = 0; ks8 < 8; ks8++) {
            const int k0 = ks8 * 8;
            qa[ks8][0] = *(const uint32_t*)&qs[r0 * HPK + k0 + tig];
            qa[ks8][1] = *(const uint32_t*)&qs[r1 * HPK + k0 + tig];
            qa[ks8][2] = *(const uint32_t*)&qs[r0 * HPK + k0 + tig + 4];
            qa[ks8][3] = *(const uint32_t*)&qs[r1 * HPK + k0 + tig + 4];
        }

        float d_o[2][4];
        #pragma unroll
        for (int nt = 0; nt < 2; nt++)
            #pragma unroll
            for (int c = 0; c < 4; c++) d_o[nt][c] = 0.f;

        for (int t = 0; t < nk; t++) {
            const bool hasNext = (t + 1 < nk);
            float* ksb = ks + (t & 1) * BK * HPK;
            float* vsb = vs + (t & 1) * BK * HPV;

            // prefetch next KV tile into registers
            float4 pk[4], pv[4];
            if (hasNext) {
                const int kb = (t + 1) * BK;
                #pragma unroll
                for (int i = 0; i < 4; i++) {
                    const int idx = tid + i * 256;
                    const int kr  = idx >> 4;
                    const int h4  = (idx & 15) << 2;
                    pk[i] = *(const float4*)&K[(kb + kr) * NH + h4];
                    pv[i] = *(const float4*)&V[(kb + kr) * NH + h4];
                }
            }

            // ---- S = Q K^T (regs) ----
            float sd[2][4];
            #pragma unroll
            for (int nt = 0; nt < 2; nt++)
                #pragma unroll
                for (int c = 0; c < 4; c++) sd[nt][c] = 0.f;

            #pragma unroll
            for (int ks8 = 0; ks8 < 8; ks8++) {
                const int k0 = ks8 * 8;
                #pragma unroll
                for (int nt = 0; nt < 2; nt++) {
                    const int n = wn * 16 + nt * 8 + gid;
                    uint32_t bb[2];
                    bb[0] = *(const uint32_t*)&ksb[n * HPK + k0 + tig];
                    bb[1] = *(const uint32_t*)&ksb[n * HPK + k0 + tig + 4];
                    mma_tf32(sd[nt], qa[ks8], bb);
                }
            }

            // ---- causal mask (regs, diagonal tile only) ----
            if (t == nk - 1) {
                #pragma unroll
                for (int nt = 0; nt < 2; nt++) {
                    const int kg = t * BK + wn * 16 + nt * 8 + 2 * tig;
                    if (kg     > q0 + r0) sd[nt][0] = -1e30f;
                    if (kg + 1 > q0 + r0) sd[nt][1] = -1e30f;
                    if (kg     > q0 + r1) sd[nt][2] = -1e30f;
                    if (kg + 1 > q0 + r1) sd[nt][3] = -1e30f;
                }
            }

            // ---- warp-partial row max -> pmax ----
            float pm0 = fmaxf(fmaxf(sd[0][0], sd[0][1]), fmaxf(sd[1][0], sd[1][1]));
            float pm1 = fmaxf(fmaxf(sd[0][2], sd[0][3]), fmaxf(sd[1][2], sd[1][3]));
            pm0 = fmaxf(pm0, __shfl_xor_sync(0xffffffffu, pm0, 1));
            pm0 = fmaxf(pm0, __shfl_xor_sync(0xffffffffu, pm0, 2));
            pm1 = fmaxf(pm1, __shfl_xor_sync(0xffffffffu, pm1, 1));
            pm1 = fmaxf(pm1, __shfl_xor_sync(0xffffffffu, pm1, 2));
            if (tig == 0) {
                pmax[r0 * 4 + wn] = pm0;
                pmax[r1 * 4 + wn] = pm1;
            }
            __syncthreads();   // A

            // ---- finalize max, exp in regs, store P, partial sums ----
            const float4 px0 = *(const float4*)&pmax[r0 * 4];
            const float4 px1 = *(const float4*)&pmax[r1 * 4];
            const float mo0 = rm[r0];
            const float mo1 = rm[r1];
            const float mn0 = fmaxf(mo0, fmaxf(fmaxf(px0.x, px0.y), fmaxf(px0.z, px0.w)));
            const float mn1 = fmaxf(mo1, fmaxf(fmaxf(px1.x, px1.y), fmaxf(px1.z, px1.w)));
            const float f0 = __expf(mo0 - mn0);
            const float f1 = __expf(mo1 - mn1);
            #pragma unroll
            for (int nt = 0; nt < 2; nt++) {
                d_o[nt][0] *= f0; d_o[nt][1] *= f0;
                d_o[nt][2] *= f1; d_o[nt][3] *= f1;
            }
            float s0 = 0.f, s1 = 0.f;
            #pragma unroll
            for (int nt = 0; nt < 2; nt++) {
                const int cb = wn * 16 + nt * 8 + 2 * tig;
                float p00 = __uint_as_float(f2tf32(__expf(sd[nt][0] - mn0)));
                float p01 = __uint_as_float(f2tf32(__expf(sd[nt][1] - mn0)));
                float p10 = __uint_as_float(f2tf32(__expf(sd[nt][2] - mn1)));
                float p11 = __uint_as_float(f2tf32(__expf(sd[nt][3] - mn1)));
                s0 += p00 + p01;
                s1 += p10 + p11;
                *(float2*)&ss[r0 * HPK + cb] = make_float2(p00, p01);
                *(float2*)&ss[r1 * HPK + cb] = make_float2(p10, p11);
            }
            s0 += __shfl_xor_sync(0xffffffffu, s0, 1);
            s0 += __shfl_xor_sync(0xffffffffu, s0, 2);
            s1 += __shfl_xor_sync(0xffffffffu, s1, 1);
            s1 += __shfl_xor_sync(0xffffffffu, s1, 2);
            if (tig == 0) {
                psum[r0 * 4 + wn] = s0;
                psum[r1 * 4 + wn] = s1;
            }

            // commit prefetched KV into other buffer (safe: barrier A ordered
            // it against last tile's PV reads; barrier B orders it vs next S)
            if (hasNext) {
                float* ksn = ks + ((t + 1) & 1) * BK * HPK;
                float* vsn = vs + ((t + 1) & 1) * BK * HPV;
                #pragma unroll
                for (int i = 0; i < 4; i++) {
                    const int idx = tid + i * 256;
                    const int kr  = idx >> 4;
                    const int h4  = (idx & 15) << 2;
                    *(uint4*)&ksn[kr * HPK + h4] = conv4(pk[i]);
                    *(uint4*)&vsn[kr * HPV + h4] = conv4(pv[i]);
                }
            }
            __syncthreads();   // B

            // ---- designated lanes update running stats ----
            if (wn == 0 && tig == 0) {
                const float4 s4 = *(const float4*)&psum[r0 * 4];
                rl[r0] = rl[r0] * f0 + (s4.x + s4.y + s4.z + s4.w);
                rm[r0] = mn0;
                const float4 t4 = *(const float4*)&psum[r1 * 4];
                rl[r1] = rl[r1] * f1 + (t4.x + t4.y + t4.z + t4.w);
                rm[r1] = mn1;
            }

            // ---- O += P V ----
            #pragma unroll
            for (int ks8 = 0; ks8 < 8; ks8++) {
                const int k0 = ks8 * 8;
                uint32_t a[4];
                a[0] = *(const uint32_t*)&ss[r0 * HPK + k0 + tig];
                a[1] = *(const uint32_t*)&ss[r1 * HPK + k0 + tig];
                a[2] = *(const uint32_t*)&ss[r0 * HPK + k0 + tig + 4];
                a[3] = *(const uint32_t*)&ss[r1 * HPK + k0 + tig + 4];
                #pragma unroll
                for (int nt = 0; nt < 2; nt++) {
                    const int n = wn * 16 + nt * 8 + gid;
                    uint32_t bb[2];
                    bb[0] = *(const uint32_t*)&vsb[(k0 + tig) * HPV + n];
                    bb[1] = *(const uint32_t*)&vsb[(k0 + tig + 4) * HPV + n];
                    mma_tf32(d_o[nt], a, bb);
                }
            }
        }

        __syncthreads();  // rl final values visible

        // ---- normalize + writeout ----
        {
            const float il0 = 1.f / rl[r0];
            const float il1 = 1.f / rl[r1];
            #pragma unroll
            for (int nt = 0; nt < 2; nt++) {
                const int cc = wn * 16 + nt * 8 + 2 * tig;
                *(float2*)&out[(b * SEQ + q0 + r0) * NH + cc] =
                    make_float2(d_o[nt][0] * il0, d_o[nt][1] * il0);
                *(float2*)&out[(b * SEQ + q0 + r1) * NH + cc] =
                    make_float2(d_o[nt][2] * il1, d_o[nt][3] * il1);
            }
        }
    }
}

// =================================================================
// launch
// =================================================================
static const int ATTN_SMEM =
    (BQ * HPK + 2 * BK * HPK + 2 * BK * HPV + BQ * HPK + 128 + 128 + 64)
    * (int)sizeof(float);

extern "C" void kernel_launch(void* const* d_in, const int* in_sizes, int n_in,
                              void* d_out, int out_size)
{
    (void)in_sizes; (void)n_in; (void)out_size;
    const float* x  = (const float*)d_in[0];
    const float* Wq = (const float*)d_in[1];
    const float* bq = (const float*)d_in[2];
    const float* Wk = (const float*)d_in[3];
    const float* bk = (const float*)d_in[4];
    const float* Wv = (const float*)d_in[5];
    const float* bv = (const float*)d_in[6];
    float* out = (float*)d_out;

    cudaFuncSetAttribute(attn_kernel,
                         cudaFuncAttributeMaxDynamicSharedMemorySize, ATTN_SMEM);

    wt_kernel<<<dim3(16, 3), 256>>>(Wq, Wk, Wv);
    qkv_mma_kernel<<<(BATCH * SEQ) / 64, 256>>>(x, bq, bk, bv);
    attn_kernel<<<dim3(32, BATCH), 256, ATTN_SMEM>>>(out);
}

// round 6
// speedup vs baseline: 2.4838x; 1.0074x over previous
#include <cuda_runtime.h>
#include <math.h>
#include <cstdint>

#define BATCH 4
#define SEQ   2048
#define DM    1024
#define NH    64

// ---------------- scratch (no cudaMalloc allowed) ----------------
__device__ float g_q[BATCH * SEQ * NH];   // tf32 bits, pre-scaled by 0.125
__device__ float g_k[BATCH * SEQ * NH];   // tf32 bits
__device__ float g_v[BATCH * SEQ * NH];   // tf32 bits
__device__ float g_wt[192 * DM];          // W^T (q|k|v rows), tf32 bits

__device__ __forceinline__ uint32_t f2tf32(float f) {
    uint32_t r;
    asm("cvt.rna.tf32.f32 %0, %1;" : "=r"(r) : "f"(f));
    return r;
}

__device__ __forceinline__ uint4 conv4(float4 v) {
    uint4 u;
    u.x = f2tf32(v.x); u.y = f2tf32(v.y);
    u.z = f2tf32(v.z); u.w = f2tf32(v.w);
    return u;
}

// mma.sync m16n8k8 tf32 (sm_80+ PTX; runs on tensor pipe)
__device__ __forceinline__ void mma_tf32(float d[4], const uint32_t a[4],
                                         const uint32_t b[2]) {
    asm volatile(
        "mma.sync.aligned.m16n8k8.row.col.f32.tf32.tf32.f32 "
        "{%0,%1,%2,%3}, {%4,%5,%6,%7}, {%8,%9}, {%0,%1,%2,%3};\n"
        : "+f"(d[0]), "+f"(d[1]), "+f"(d[2]), "+f"(d[3])
        : "r"(a[0]), "r"(a[1]), "r"(a[2]), "r"(a[3]),
          "r"(b[0]), "r"(b[1]));
}

// =================================================================
// Kernel 0: transpose W (q|k|v) -> g_wt[192][1024], tf32-rounded.
// =================================================================
__global__ __launch_bounds__(256) void wt_kernel(
    const float* __restrict__ Wq,
    const float* __restrict__ Wk,
    const float* __restrict__ Wv)
{
    __shared__ float t[64][65];
    const int tid = threadIdx.x;
    const int k0  = blockIdx.x * 64;
    const int y   = blockIdx.y;
    const float* W = (y == 0) ? Wq : (y == 1) ? Wk : Wv;

    #pragma unroll
    for (int i = 0; i < 16; i++) {
        const int idx = tid + i * 256;
        const int kk = idx >> 6, nn = idx & 63;
        t[kk][nn] = W[(k0 + kk) * NH + nn];
    }
    __syncthreads();
    #pragma unroll
    for (int i = 0; i < 16; i++) {
        const int idx = tid + i * 256;
        const int nn = idx >> 6, kk = idx & 63;
        g_wt[(y * 64 + nn) * DM + k0 + kk] = __uint_as_float(f2tf32(t[kk][nn]));
    }
}

// =================================================================
// Kernel 1: QKV projection via mma.sync tf32.
// Epilogue now rounds outputs to tf32 and pre-scales q (and bq) by 0.125
// so the attention kernel is conversion-free.
// =================================================================
#define APAD 36

__global__ __launch_bounds__(256) void qkv_mma_kernel(
    const float* __restrict__ x,
    const float* __restrict__ bq,
    const float* __restrict__ bk,
    const float* __restrict__ bv)
{
    __shared__ float As[64][APAD];
    __shared__ float Bs[192][APAD];
    __shared__ float bias_sm[192];

    const int tid  = threadIdx.x;
    const int wid  = tid >> 5;
    const int lane = tid & 31;
    const int m0   = blockIdx.x * 64;
    const int wm   = wid >> 2;
    const int wn   = wid & 3;

    if (tid < 64)        bias_sm[tid] = bq[tid];
    else if (tid < 128)  bias_sm[tid] = bk[tid - 64];
    else if (tid < 192)  bias_sm[tid] = bv[tid - 128];

    const int gid = lane >> 2;
    const int tig = lane & 3;

    float d[2][6][4];
    #pragma unroll
    for (int i = 0; i < 2; i++)
        #pragma unroll
        for (int j = 0; j < 6; j++)
            #pragma unroll
            for (int c = 0; c < 4; c++) d[i][j][c] = 0.f;

    float4 ra[2], rb[6];
    #pragma unroll
    for (int i = 0; i < 2; i++) {
        const int idx = tid + i * 256;
        ra[i] = *(const float4*)&x[(size_t)(m0 + (idx >> 3)) * DM + ((idx & 7) << 2)];
    }
    #pragma unroll
    for (int i = 0; i < 6; i++) {
        const int idx = tid + i * 256;
        rb[i] = *(const float4*)&g_wt[(size_t)(idx >> 3) * DM + ((idx & 7) << 2)];
    }

    for (int kc = 0; kc < DM; kc += 32) {
        #pragma unroll
        for (int i = 0; i < 2; i++) {
            const int idx = tid + i * 256;
            *(uint4*)&As[idx >> 3][(idx & 7) << 2] = conv4(ra[i]);
        }
        #pragma unroll
        for (int i = 0; i < 6; i++) {
            const int idx = tid + i * 256;
            *(float4*)&Bs[idx >> 3][(idx & 7) << 2] = rb[i];
        }
        __syncthreads();

        if (kc + 32 < DM) {
            const int kn = kc + 32;
            #pragma unroll
            for (int i = 0; i < 2; i++) {
                const int idx = tid + i * 256;
                ra[i] = *(const float4*)&x[(size_t)(m0 + (idx >> 3)) * DM + kn + ((idx & 7) << 2)];
            }
            #pragma unroll
            for (int i = 0; i < 6; i++) {
                const int idx = tid + i * 256;
                rb[i] = *(const float4*)&g_wt[(size_t)(idx >> 3) * DM + kn + ((idx & 7) << 2)];
            }
        }

        #pragma unroll
        for (int ks = 0; ks < 4; ks++) {
            const int k0 = ks * 8;
            uint32_t a[2][4];
            #pragma unroll
            for (int mt = 0; mt < 2; mt++) {
                const int r = wm * 32 + mt * 16 + gid;
                a[mt][0] = *(const uint32_t*)&As[r][k0 + tig];
                a[mt][1] = *(const uint32_t*)&As[r + 8][k0 + tig];
                a[mt][2] = *(const uint32_t*)&As[r][k0 + tig + 4];
                a[mt][3] = *(const uint32_t*)&As[r + 8][k0 + tig + 4];
            }
            #pragma unroll
            for (int nt = 0; nt < 6; nt++) {
                const int n = wn * 48 + nt * 8 + gid;
                uint32_t b[2];
                b[0] = *(const uint32_t*)&Bs[n][k0 + tig];
                b[1] = *(const uint32_t*)&Bs[n][k0 + tig + 4];
                mma_tf32(d[0][nt], a[0], b);
                mma_tf32(d[1][nt], a[1], b);
            }
        }
        __syncthreads();
    }

    #pragma unroll
    for (int mt = 0; mt < 2; mt++) {
        const int row = m0 + wm * 32 + mt * 16 + gid;
        #pragma unroll
        for (int nt = 0; nt < 6; nt++) {
            const int col0 = wn * 48 + nt * 8;
            float* dst = (col0 < 64) ? g_q : (col0 < 128) ? g_k : g_v;
            const float scale = (col0 < 64) ? 0.125f : 1.0f;
            const int h0 = (col0 & 63) + 2 * tig;
            const float b0 = bias_sm[col0 + 2 * tig];
            const float b1 = bias_sm[col0 + 2 * tig + 1];
            uint2 w0 = make_uint2(f2tf32((d[mt][nt][0] + b0) * scale),
                                  f2tf32((d[mt][nt][1] + b1) * scale));
            uint2 w1 = make_uint2(f2tf32((d[mt][nt][2] + b0) * scale),
                                  f2tf32((d[mt][nt][3] + b1) * scale));
            *(uint2*)&dst[(size_t)row * NH + h0]       = w0;
            *(uint2*)&dst[(size_t)(row + 8) * NH + h0] = w1;
        }
    }
}

// =================================================================
// Kernel 2: causal flash attention, mma.sync tf32.
// Cross-tile pipeline: PV(t) interleaved with S(t+1) (4 independent
// accumulator sets), double-buffered P, K committed one tile ahead of V.
// 2 barriers per tile. All inputs pre-rounded tf32 (no cvt here).
// =================================================================
#define BQ  32
#define BK  64
#define HPK 68
#define HPV 72

__global__ __launch_bounds__(256) void attn_kernel(float* __restrict__ out)
{
    extern __shared__ float sm[];
    float* qs   = sm;                     // [32][68]
    float* ks   = qs + BQ * HPK;          // [2][64][68]
    float* vs   = ks + 2 * BK * HPK;      // [2][64][72]
    float* ss   = vs + 2 * BK * HPV;      // [2][32][68] P (exp'd, tf32)
    float* pmax = ss + 2 * BQ * HPK;      // [32][4]
    float* psum = pmax + 128;             // [32][4]
    float* rm   = psum + 128;             // [32]
    float* rl   = rm + 32;                // [32]

    const int tid  = threadIdx.x;
    const int b    = blockIdx.y;
    const int pair = blockIdx.x;

    const float* Q = g_q + b * SEQ * NH;
    const float* K = g_k + b * SEQ * NH;
    const float* V = g_v + b * SEQ * NH;

    const int wid  = tid >> 5;
    const int lane = tid & 31;
    const int gid  = lane >> 2;
    const int tig  = lane & 3;
    const int wm   = wid >> 2;
    const int wn   = wid & 3;
    const int r0   = wm * 16 + gid;
    const int r1   = r0 + 8;

    const int lkr  = tid >> 4;            // KV load: row lkr + 16i
    const int lh4  = (tid & 15) << 2;

    for (int sub = 0; sub < 2; sub++) {
        const int qt = (sub == 0) ? pair : (63 - pair);
        const int q0 = qt * BQ;
        const int nk = (q0 + BQ + BK - 1) / BK;

        __syncthreads();  // previous subtile fully done

        // Q copy (already tf32 + pre-scaled)
        #pragma unroll
        for (int it = 0; it < 2; it++) {
            const int i  = tid + it * 256;
            const int r  = i >> 4;
            const int h4 = (i & 15) << 2;
            *(float4*)&qs[r * HPK + h4] = *(const float4*)&Q[(q0 + r) * NH + h4];
        }
        if (tid < BQ) { rm[tid] = -1e30f; rl[tid] = 0.f; }

        // K(0) commit direct; V(0), K(1) into registers
        float4 pk[4], pv[4];
        #pragma unroll
        for (int i = 0; i < 4; i++) {
            const int kr = lkr + 16 * i;
            *(float4*)&ks[kr * HPK + lh4] = *(const float4*)&K[kr * NH + lh4];
            pv[i] = *(const float4*)&V[kr * NH + lh4];
        }
        if (nk > 1) {
            #pragma unroll
            for (int i = 0; i < 4; i++) {
                const int kr = BK + lkr + 16 * i;
                pk[i] = *(const float4*)&K[kr * NH + lh4];
            }
        }
        __syncthreads();

        // hoist Q A-fragments
        uint32_t qa[8][4];
        #pragma unroll
        for (int ks8 = 0; ks8 < 8; ks8++) {
            const int k0 = ks8 * 8;
            qa[ks8][0] = *(const uint32_t*)&qs[r0 * HPK + k0 + tig];
            qa[ks8][1] = *(const uint32_t*)&qs[r1 * HPK + k0 + tig];
            qa[ks8][2] = *(const uint32_t*)&qs[r0 * HPK + k0 + tig + 4];
            qa[ks8][3] = *(const uint32_t*)&qs[r1 * HPK + k0 + tig + 4];
        }

        float d_o[2][4];
        #pragma unroll
        for (int nt = 0; nt < 2; nt++)
            #pragma unroll
            for (int c = 0; c < 4; c++) d_o[nt][c] = 0.f;

        // pipeline: t = -1 is the S(0) prologue
        for (int t = -1; t < nk; t++) {
            const bool hasNext = (t + 1 < nk);
            float sd[2][4];
            #pragma unroll
            for (int nt = 0; nt < 2; nt++)
                #pragma unroll
                for (int c = 0; c < 4; c++) sd[nt][c] = 0.f;

            if (t >= 0) {
                // ---- PV(t) interleaved with S(t+1) ----
                float* ssA = ss + (t & 1) * BQ * HPK;
                float* vsb = vs + (t & 1) * BK * HPV;
                float* ksn = ks + ((t + 1) & 1) * BK * HPK;
                #pragma unroll
                for (int ks8 = 0; ks8 < 8; ks8++) {
                    const int k0 = ks8 * 8;
                    uint32_t a[4];
                    a[0] = *(const uint32_t*)&ssA[r0 * HPK + k0 + tig];
                    a[1] = *(const uint32_t*)&ssA[r1 * HPK + k0 + tig];
                    a[2] = *(const uint32_t*)&ssA[r0 * HPK + k0 + tig + 4];
                    a[3] = *(const uint32_t*)&ssA[r1 * HPK + k0 + tig + 4];
                    #pragma unroll
                    for (int nt = 0; nt < 2; nt++) {
                        const int n = wn * 16 + nt * 8 + gid;
                        uint32_t bb[2];
                        bb[0] = *(const uint32_t*)&vsb[(k0 + tig) * HPV + n];
                        bb[1] = *(const uint32_t*)&vsb[(k0 + tig + 4) * HPV + n];
                        mma_tf32(d_o[nt], a, bb);
                    }
                    if (hasNext) {
                        #pragma unroll
                        for (int nt = 0; nt < 2; nt++) {
                            const int n = wn * 16 + nt * 8 + gid;
                            uint32_t bb[2];
                            bb[0] = *(const uint32_t*)&ksn[n * HPK + k0 + tig];
                            bb[1] = *(const uint32_t*)&ksn[n * HPK + k0 + tig + 4];
                            mma_tf32(sd[nt], qa[ks8], bb);
                        }
                    }
                }
            } else {
                // ---- prologue: S(0) only ----
                #pragma unroll
                for (int ks8 = 0; ks8 < 8; ks8++) {
                    const int k0 = ks8 * 8;
                    #pragma unroll
                    for (int nt = 0; nt < 2; nt++) {
                        const int n = wn * 16 + nt * 8 + gid;
                        uint32_t bb[2];
                        bb[0] = *(const uint32_t*)&ks[n * HPK + k0 + tig];
                        bb[1] = *(const uint32_t*)&ks[n * HPK + k0 + tig + 4];
                        mma_tf32(sd[nt], qa[ks8], bb);
                    }
                }
            }

            if (hasNext) {
                const int tt = t + 1;

                // causal mask (diagonal tile only)
                if (tt == nk - 1) {
                    #pragma unroll
                    for (int nt = 0; nt < 2; nt++) {
                        const int kg = tt * BK + wn * 16 + nt * 8 + 2 * tig;
                        if (kg     > q0 + r0) sd[nt][0] = -1e30f;
                        if (kg + 1 > q0 + r0) sd[nt][1] = -1e30f;
                        if (kg     > q0 + r1) sd[nt][2] = -1e30f;
                        if (kg + 1 > q0 + r1) sd[nt][3] = -1e30f;
                    }
                }

                // warp-partial row max
                float pm0 = fmaxf(fmaxf(sd[0][0], sd[0][1]), fmaxf(sd[1][0], sd[1][1]));
                float pm1 = fmaxf(fmaxf(sd[0][2], sd[0][3]), fmaxf(sd[1][2], sd[1][3]));
                pm0 = fmaxf(pm0, __shfl_xor_sync(0xffffffffu, pm0, 1));
                pm0 = fmaxf(pm0, __shfl_xor_sync(0xffffffffu, pm0, 2));
                pm1 = fmaxf(pm1, __shfl_xor_sync(0xffffffffu, pm1, 1));
                pm1 = fmaxf(pm1, __shfl_xor_sync(0xffffffffu, pm1, 2));
                if (tig == 0) {
                    pmax[r0 * 4 + wn] = pm0;
                    pmax[r1 * 4 + wn] = pm1;
                }
                __syncthreads();   // A

                // finalize max, exp, rescale O, store P, partial sums
                const float4 px0 = *(const float4*)&pmax[r0 * 4];
                const float4 px1 = *(const float4*)&pmax[r1 * 4];
                const float mo0 = rm[r0];
                const float mo1 = rm[r1];
                const float mn0 = fmaxf(mo0, fmaxf(fmaxf(px0.x, px0.y), fmaxf(px0.z, px0.w)));
                const float mn1 = fmaxf(mo1, fmaxf(fmaxf(px1.x, px1.y), fmaxf(px1.z, px1.w)));
                const float f0 = __expf(mo0 - mn0);
                const float f1 = __expf(mo1 - mn1);
                #pragma unroll
                for (int nt = 0; nt < 2; nt++) {
                    d_o[nt][0] *= f0; d_o[nt][1] *= f0;
                    d_o[nt][2] *= f1; d_o[nt][3] *= f1;
                }
                float* ssN = ss + (tt & 1) * BQ * HPK;
                float s0 = 0.f, s1 = 0.f;
                #pragma unroll
                for (int nt = 0; nt < 2; nt++) {
                    const int cb = wn * 16 + nt * 8 + 2 * tig;
                    float p00 = __uint_as_float(f2tf32(__expf(sd[nt][0] - mn0)));
                    float p01 = __uint_as_float(f2tf32(__expf(sd[nt][1] - mn0)));
                    float p10 = __uint_as_float(f2tf32(__expf(sd[nt][2] - mn1)));
                    float p11 = __uint_as_float(f2tf32(__expf(sd[nt][3] - mn1)));
                    s0 += p00 + p01;
                    s1 += p10 + p11;
                    *(float2*)&ssN[r0 * HPK + cb] = make_float2(p00, p01);
                    *(float2*)&ssN[r1 * HPK + cb] = make_float2(p10, p11);
                }
                s0 += __shfl_xor_sync(0xffffffffu, s0, 1);
                s0 += __shfl_xor_sync(0xffffffffu, s0, 2);
                s1 += __shfl_xor_sync(0xffffffffu, s1, 1);
                s1 += __shfl_xor_sync(0xffffffffu, s1, 2);
                if (tig == 0) {
                    psum[r0 * 4 + wn] = s0;
                    psum[r1 * 4 + wn] = s1;
                }

                // commit V(t+1); commit K(t+2); prefetch K(t+3), V(t+2)
                {
                    float* vsn = vs + (tt & 1) * BK * HPV;
                    #pragma unroll
                    for (int i = 0; i < 4; i++)
                        *(float4*)&vsn[(lkr + 16 * i) * HPV + lh4] = pv[i];
                }
                if (t + 2 < nk) {
                    float* ksn2 = ks + (t & 1) * BK * HPK;
                    #pragma unroll
                    for (int i = 0; i < 4; i++)
                        *(float4*)&ksn2[(lkr + 16 * i) * HPK + lh4] = pk[i];
                }
                if (t + 3 < nk) {
                    const int kb = (t + 3) * BK;
                    #pragma unroll
                    for (int i = 0; i < 4; i++)
                        pk[i] = *(const float4*)&K[(kb + lkr + 16 * i) * NH + lh4];
                }
                if (t + 2 < nk) {
                    const int kb = (t + 2) * BK;
                    #pragma unroll
                    for (int i = 0; i < 4; i++)
                        pv[i] = *(const float4*)&V[(kb + lkr + 16 * i) * NH + lh4];
                }
                __syncthreads();   // B

                // designated lanes update running stats
                if (wn == 0 && tig == 0) {
                    const float4 s4 = *(const float4*)&psum[r0 * 4];
                    rl[r0] = rl[r0] * f0 + (s4.x + s4.y + s4.z + s4.w);
                    rm[r0] = mn0;
                    const float4 t4 = *(const float4*)&psum[r1 * 4];
                    rl[r1] = rl[r1] * f1 + (t4.x + t4.y + t4.z + t4.w);
                    rm[r1] = mn1;
                }
            }
        }

        __syncthreads();  // rl final values visible

        // ---- normalize + writeout ----
        {
            const float il0 = 1.f / rl[r0];
            const float il1 = 1.f / rl[r1];
            #pragma unroll
            for (int nt = 0; nt < 2; nt++) {
                const int cc = wn * 16 + nt * 8 + 2 * tig;
                *(float2*)&out[(b * SEQ + q0 + r0) * NH + cc] =
                    make_float2(d_o[nt][0] * il0, d_o[nt][1] * il0);
                *(float2*)&out[(b * SEQ + q0 + r1) * NH + cc] =
                    make_float2(d_o[nt][2] * il1, d_o[nt][3] * il1);
            }
        }
    }
}

// =================================================================
// launch
// =================================================================
static const int ATTN_SMEM =
    (BQ * HPK + 2 * BK * HPK + 2 * BK * HPV + 2 * BQ * HPK + 128 + 128 + 64)
    * (int)sizeof(float);

extern "C" void kernel_launch(void* const* d_in, const int* in_sizes, int n_in,
                              void* d_out, int out_size)
{
    (void)in_sizes; (void)n_in; (void)out_size;
    const float* x  = (const float*)d_in[0];
    const float* Wq = (const float*)d_in[1];
    const float* bq = (const float*)d_in[2];
    const float* Wk = (const float*)d_in[3];
    const float* bk = (const float*)d_in[4];
    const float* Wv = (const float*)d_in[5];
    const float* bv = (const float*)d_in[6];
    float* out = (float*)d_out;

    cudaFuncSetAttribute(attn_kernel,
                         cudaFuncAttributeMaxDynamicSharedMemorySize, ATTN_SMEM);

    wt_kernel<<<dim3(16, 3), 256>>>(Wq, Wk, Wv);
    qkv_mma_kernel<<<(BATCH * SEQ) / 64, 256>>>(x, bq, bk, bv);
    attn_kernel<<<dim3(32, BATCH), 256, ATTN_SMEM>>>(out);
}